// round 15
// baseline (speedup 1.0000x reference)
#include <cuda_runtime.h>
#include <cuda_fp16.h>
#include <cstdint>

#define HDIM 2048
#define MDIM 1408
#define NEXP 8
#define NTOK 1024

// ---------------- device scratch ----------------
__device__ __half g_xh[NTOK * HDIM];                // x, single fp16 plane
__device__ __half g_act[(NEXP + 1) * NTOK * MDIM];  // activations, single fp16 plane
__device__ __half g_wgh[(NEXP + 1) * MDIM * HDIM];
__device__ __half g_wuh[(NEXP + 1) * MDIM * HDIM];
__device__ __half g_wdh[(NEXP + 1) * HDIM * MDIM];
__device__ int   g_tok[NEXP * NTOK];
__device__ float g_wt[NEXP * NTOK];
__device__ int   g_cnt[NEXP];
__device__ float g_pisum[NEXP];

// ---------------- helpers ----------------
__device__ __forceinline__ uint32_t smem_u32(const void* p) {
    uint32_t a;
    asm("{ .reg .u64 t; cvta.to.shared.u64 t, %1; cvt.u32.u64 %0, t; }" : "=r"(a) : "l"(p));
    return a;
}
__device__ __forceinline__ void cp16(uint32_t dst, const void* src) {
    asm volatile("cp.async.cg.shared.global [%0], [%1], 16;" :: "r"(dst), "l"(src));
}
#define CP_COMMIT() asm volatile("cp.async.commit_group;" ::: "memory")
#define CP_WAIT1()  asm volatile("cp.async.wait_group 1;" ::: "memory")

#define LDSM4(r, addr)                                                                       \
    asm volatile("ldmatrix.sync.aligned.m8n8.x4.shared.b16 {%0,%1,%2,%3}, [%4];"             \
                 : "=r"((r)[0]), "=r"((r)[1]), "=r"((r)[2]), "=r"((r)[3]) : "r"(addr))
#define LDSM2(r, addr)                                                                       \
    asm volatile("ldmatrix.sync.aligned.m8n8.x2.shared.b16 {%0,%1}, [%2];"                   \
                 : "=r"((r)[0]), "=r"((r)[1]) : "r"(addr))
#define MMA(c, a, b)                                                                         \
    asm volatile("mma.sync.aligned.m16n8k16.row.col.f32.f16.f16.f32 "                        \
                 "{%0,%1,%2,%3},{%4,%5,%6,%7},{%8,%9},{%0,%1,%2,%3};"                        \
                 : "+f"((c)[0]), "+f"((c)[1]), "+f"((c)[2]), "+f"((c)[3])                    \
                 : "r"((a)[0]), "r"((a)[1]), "r"((a)[2]), "r"((a)[3]), "r"((b)[0]), "r"((b)[1]))

__device__ __forceinline__ uint32_t hpack2(float a, float b) {
    __half2 hp = __halves2half2(__float2half(a), __float2half(b));
    return *reinterpret_cast<uint32_t*>(&hp);
}

#define LDS_ROW 80   // 32 fp16 + 16B pad -> conflict-free ldmatrix

// ---------------- init / conversions ----------------
__global__ void zeroy_kernel(float* __restrict__ y) {
    int i = blockIdx.x * blockDim.x + threadIdx.x;
    if (i < NTOK * HDIM) y[i] = 0.f;
}

__global__ void xconv_kernel(const float* __restrict__ x) {
    int i = blockIdx.x * blockDim.x + threadIdx.x;
    if (i < NTOK * HDIM) g_xh[i] = __float2half(x[i]);
    if (i < NEXP) { g_cnt[i] = 0; g_pisum[i] = 0.f; }
}

__global__ __launch_bounds__(256)
void wconv_all(const float4* __restrict__ wg, const float4* __restrict__ wu,
               const float4* __restrict__ wd, const float4* __restrict__ sg,
               const float4* __restrict__ su, const float4* __restrict__ sd) {
    const int NE4 = NEXP * MDIM * HDIM / 4;
    const int NT4 = (NEXP + 1) * MDIM * HDIM / 4;
    int i = blockIdx.x * blockDim.x + threadIdx.x;
    if (i >= NT4) return;
    int which = blockIdx.y;
    __half* hb;
    const float4 *rsrc, *ssrc;
    if (which == 0)      { hb = g_wgh; rsrc = wg; ssrc = sg; }
    else if (which == 1) { hb = g_wuh; rsrc = wu; ssrc = su; }
    else                 { hb = g_wdh; rsrc = wd; ssrc = sd; }
    float4 v = (i < NE4) ? rsrc[i] : ssrc[i - NE4];
    uint2 h;
    h.x = hpack2(v.x, v.y);
    h.y = hpack2(v.z, v.w);
    ((uint2*)hb)[i] = h;
}

// ---------------- gate ----------------
__global__ __launch_bounds__(256)
void gate_kernel(const float* __restrict__ x, const float* __restrict__ gw) {
    const int t = blockIdx.x;
    const float* xr = x + (size_t)t * HDIM;
    float acc[NEXP];
#pragma unroll
    for (int e = 0; e < NEXP; e++) acc[e] = 0.f;
    for (int h = threadIdx.x; h < HDIM; h += 256) {
        float xv = xr[h];
#pragma unroll
        for (int e = 0; e < NEXP; e++) acc[e] = fmaf(xv, gw[e * HDIM + h], acc[e]);
    }
#pragma unroll
    for (int e = 0; e < NEXP; e++)
        for (int o = 16; o > 0; o >>= 1) acc[e] += __shfl_down_sync(0xffffffffu, acc[e], o);

    __shared__ float red[8][NEXP];
    int warp = threadIdx.x >> 5, lane = threadIdx.x & 31;
    if (lane == 0) {
#pragma unroll
        for (int e = 0; e < NEXP; e++) red[warp][e] = acc[e];
    }
    __syncthreads();
    if (threadIdx.x == 0) {
        float lg[NEXP];
#pragma unroll
        for (int e = 0; e < NEXP; e++) {
            float s = 0.f;
            for (int w = 0; w < 8; w++) s += red[w][e];
            lg[e] = s;
        }
        float mx = lg[0];
#pragma unroll
        for (int e = 1; e < NEXP; e++) mx = fmaxf(mx, lg[e]);
        float p[NEXP]; float den = 0.f;
#pragma unroll
        for (int e = 0; e < NEXP; e++) { p[e] = __expf(lg[e] - mx); den += p[e]; }
#pragma unroll
        for (int e = 0; e < NEXP; e++) p[e] /= den;
#pragma unroll
        for (int e = 0; e < NEXP; e++) atomicAdd(&g_pisum[e], p[e]);
        int i1 = 0;
#pragma unroll
        for (int e = 1; e < NEXP; e++) if (p[e] > p[i1]) i1 = e;
        int i2 = -1;
#pragma unroll
        for (int e = 0; e < NEXP; e++) {
            if (e == i1) continue;
            if (i2 < 0 || p[e] > p[i2]) i2 = e;
        }
        float w1 = p[i1], w2 = p[i2];
        float s2 = w1 + w2 + 1e-20f;
        w1 /= s2; w2 /= s2;
        int pos1 = atomicAdd(&g_cnt[i1], 1);
        g_tok[i1 * NTOK + pos1] = t; g_wt[i1 * NTOK + pos1] = w1;
        int pos2 = atomicAdd(&g_cnt[i2], 1);
        g_tok[i2 * NTOK + pos2] = t; g_wt[i2 * NTOK + pos2] = w2;
    }
}

// =======================================================================
// gateup: act = silu(X Wg^T) * (X Wu^T)
// tile 64x64, 128 thr, K chunk 32, 3-stage, 4 CTAs/SM
// =======================================================================
#define GU_STAGE 15360
#define GU_A   0
#define GU_BG  5120
#define GU_BU  10240
#define GU_TOK (3 * GU_STAGE)
#define GU_SM  (GU_TOK + 256)

__global__ __launch_bounds__(128, 4)
void gateup_mma() {
    extern __shared__ __align__(128) char sm[];
    const int z = blockIdx.z;
    const bool SH = (z == NEXP);
    const int nrows = SH ? NTOK : g_cnt[z];
    const int row0 = blockIdx.x * 64;
    if (row0 >= nrows) return;
    const int n0 = blockIdx.y * 64;

    const int tid = threadIdx.x, wid = tid >> 5, lane = tid & 31;
    int* toks = (int*)(sm + GU_TOK);
    if (tid < 64) {
        int r = row0 + tid;
        toks[tid] = (r < nrows) ? (SH ? r : g_tok[z * NTOK + r]) : 0;
    }
    __syncthreads();

    const uint32_t sb = smem_u32(sm);

    // A cp: 2 thr/row, 2 cp16 each (64 rows x 64B)
    const int arow = tid >> 1, aseg = tid & 1;
    const __half* ap = g_xh + (size_t)toks[arow] * HDIM + aseg * 16;
    const uint32_t aD = sb + GU_A + arow * LDS_ROW + aseg * 32;

    // B cp: plane = tid>>6 (g,u), row = tid&63, 4 cp16 each
    const int bpl = tid >> 6, brow = tid & 63;
    const size_t bOff = ((size_t)z * MDIM + n0 + brow) * HDIM;
    const __half* pb = (bpl == 0 ? g_wgh : g_wuh) + bOff;
    const uint32_t bD = sb + (bpl == 0 ? GU_BG : GU_BU) + brow * LDS_ROW;

#define GU_CP(c) do { uint32_t o = ((c) % 3) * GU_STAGE; size_t ko = (size_t)(c) * 32; \
    cp16(aD + o,      ap + ko);      cp16(aD + o + 16, ap + ko + 8);                   \
    cp16(bD + o,      pb + ko);      cp16(bD + o + 16, pb + ko + 8);                   \
    cp16(bD + o + 32, pb + ko + 16); cp16(bD + o + 48, pb + ko + 24); } while (0)

    // fragments: warp grid 2m x 2n; warp tile 32x32 (dual g/u acc)
    const int wm = wid & 1, wn = wid >> 1;
    const uint32_t aOffL = (lane & 15) * LDS_ROW + (lane >> 4) * 16;
    const uint32_t bOffL = (lane & 7) * LDS_ROW + ((lane >> 3) & 1) * 16;
    const uint32_t aB = sb + GU_A + (wm * 32) * LDS_ROW + aOffL;
    const uint32_t bGB = sb + GU_BG + (wn * 32) * LDS_ROW + bOffL;
    const uint32_t bUB = sb + GU_BU + (wn * 32) * LDS_ROW + bOffL;

    float accg[2][4][4] = {}, accu[2][4][4] = {};

    const int NC = HDIM / 32;
    GU_CP(0); CP_COMMIT();
    GU_CP(1); CP_COMMIT();

    for (int c = 0; c < NC; c++) {
        const uint32_t so = (c % 3) * GU_STAGE;
        CP_WAIT1();
        __syncthreads();
        if (c + 2 < NC) GU_CP(c + 2);
        CP_COMMIT();   // one commit per iter (possibly empty) keeps wait_group invariant
#pragma unroll
        for (int ks = 0; ks < 2; ks++) {
            uint32_t ah[2][4];
#pragma unroll
            for (int i = 0; i < 2; i++)
                LDSM4(ah[i], aB + so + i * (16 * LDS_ROW) + ks * 32);
            uint32_t bgh[4][2], buh[4][2];
#pragma unroll
            for (int j = 0; j < 4; j++) {
                LDSM2(bgh[j], bGB + so + j * (8 * LDS_ROW) + ks * 32);
                LDSM2(buh[j], bUB + so + j * (8 * LDS_ROW) + ks * 32);
            }
#pragma unroll
            for (int i = 0; i < 2; i++)
#pragma unroll
                for (int j = 0; j < 4; j++) {
                    MMA(accg[i][j], ah[i], bgh[j]);
                    MMA(accu[i][j], ah[i], buh[j]);
                }
        }
    }

    // epilogue: silu(g)*u -> single fp16 plane
    const int mrow = wm * 32 + (lane >> 2);
    const int col0 = n0 + wn * 32 + (lane & 3) * 2;
#pragma unroll
    for (int i = 0; i < 2; i++)
#pragma unroll
        for (int j = 0; j < 4; j++) {
            int col = col0 + j * 8;
#pragma unroll
            for (int half = 0; half < 2; half++) {
                int r = row0 + mrow + i * 16 + half * 8;
                if (r < nrows) {
                    float gv0 = accg[i][j][half * 2],     uv0 = accu[i][j][half * 2];
                    float gv1 = accg[i][j][half * 2 + 1], uv1 = accu[i][j][half * 2 + 1];
                    float a0 = (gv0 / (1.f + __expf(-gv0))) * uv0;
                    float a1 = (gv1 / (1.f + __expf(-gv1))) * uv1;
                    size_t idx = ((size_t)z * NTOK + r) * MDIM + col;
                    *(uint32_t*)(g_act + idx) = hpack2(a0, a1);
                }
            }
        }
#undef GU_CP
}

// =======================================================================
// down: y[tok] += w * (act @ Wd^T)
// tile 64x128, 128 thr, K chunk 32, 3-stage, 4 CTAs/SM
// =======================================================================
#define DN_STAGE 15360
#define DN_A   0
#define DN_B   5120
#define DN_TOK (3 * DN_STAGE)
#define DN_WTS (DN_TOK + 256)
#define DN_SM  (DN_WTS + 256)

__global__ __launch_bounds__(128, 4)
void down_mma(float* __restrict__ y) {
    extern __shared__ __align__(128) char sm[];
    const int z = blockIdx.z;
    const bool SH = (z == NEXP);
    const int nrows = SH ? NTOK : g_cnt[z];
    const int row0 = blockIdx.x * 64;
    if (row0 >= nrows) return;
    const int h0 = blockIdx.y * 128;

    const int tid = threadIdx.x, wid = tid >> 5, lane = tid & 31;
    int* toks = (int*)(sm + DN_TOK);
    float* wts = (float*)(sm + DN_WTS);
    if (tid < 64) {
        int r = row0 + tid;
        if (r < nrows) {
            toks[tid] = SH ? r : g_tok[z * NTOK + r];
            wts[tid]  = SH ? 1.f : g_wt[z * NTOK + r];
        } else { toks[tid] = 0; wts[tid] = 0.f; }
    }
    __syncthreads();

    const uint32_t sb = smem_u32(sm);

    // A cp: 2 thr/row, 2 cp16 (64 rows x 64B)
    const int arow = tid >> 1, aseg = tid & 1;
    const __half* ap = g_act + ((size_t)z * NTOK + row0 + arow) * MDIM + aseg * 16;
    const uint32_t aD = sb + DN_A + arow * LDS_ROW + aseg * 32;

    // B cp: 1 thr/row (128 rows), 4 cp16 each
    const size_t bOff = ((size_t)z * HDIM + h0 + tid) * MDIM;
    const __half* pb = g_wdh + bOff;
    const uint32_t bD = sb + DN_B + tid * LDS_ROW;

#define DN_CP(c) do { uint32_t o = ((c) % 3) * DN_STAGE; size_t ko = (size_t)(c) * 32; \
    cp16(aD + o,      ap + ko);      cp16(aD + o + 16, ap + ko + 8);                   \
    cp16(bD + o,      pb + ko);      cp16(bD + o + 16, pb + ko + 8);                   \
    cp16(bD + o + 32, pb + ko + 16); cp16(bD + o + 48, pb + ko + 24); } while (0)

    // fragments: warp grid 2m x 2n; warp tile 32x64
    const int wm = wid & 1, wn = wid >> 1;
    const uint32_t aOffL = (lane & 15) * LDS_ROW + (lane >> 4) * 16;
    const uint32_t bOffL = (lane & 7) * LDS_ROW + ((lane >> 3) & 1) * 16;
    const uint32_t aB = sb + DN_A + (wm * 32) * LDS_ROW + aOffL;
    const uint32_t bB = sb + DN_B + (wn * 64) * LDS_ROW + bOffL;

    float acc[2][8][4] = {};

    const int NC = MDIM / 32;
    DN_CP(0); CP_COMMIT();
    DN_CP(1); CP_COMMIT();

    for (int c = 0; c < NC; c++) {
        const uint32_t so = (c % 3) * DN_STAGE;
        CP_WAIT1();
        __syncthreads();
        if (c + 2 < NC) DN_CP(c + 2);
        CP_COMMIT();
#pragma unroll
        for (int ks = 0; ks < 2; ks++) {
            uint32_t ah[2][4];
#pragma unroll
            for (int i = 0; i < 2; i++)
                LDSM4(ah[i], aB + so + i * (16 * LDS_ROW) + ks * 32);
            uint32_t bh[8][2];
#pragma unroll
            for (int j = 0; j < 8; j++)
                LDSM2(bh[j], bB + so + j * (8 * LDS_ROW) + ks * 32);
#pragma unroll
            for (int i = 0; i < 2; i++)
#pragma unroll
                for (int j = 0; j < 8; j++)
                    MMA(acc[i][j], ah[i], bh[j]);
        }
    }

    // epilogue: weighted atomic scatter
    const int mrow = wm * 32 + (lane >> 2);
    const int col0 = h0 + wn * 64 + (lane & 3) * 2;
#pragma unroll
    for (int i = 0; i < 2; i++)
#pragma unroll
        for (int half = 0; half < 2; half++) {
            int rl = mrow + i * 16 + half * 8;
            int r = row0 + rl;
            if (r < nrows) {
                float w = wts[rl];
                int tok = toks[rl];
                float* yp = y + (size_t)tok * HDIM;
#pragma unroll
                for (int j = 0; j < 8; j++) {
                    int col = col0 + j * 8;
                    atomicAdd(&yp[col],     acc[i][j][half * 2]     * w);
                    atomicAdd(&yp[col + 1], acc[i][j][half * 2 + 1] * w);
                }
            }
        }
#undef DN_CP
}

// ---------------- aux loss ----------------
__global__ void aux_kernel(float* __restrict__ p) {
    float a = 0.f;
#pragma unroll
    for (int e = 0; e < NEXP; e++) {
        float ce = (float)g_cnt[e] * ((float)NEXP / (float)(NTOK * 2));
        float pi = g_pisum[e] / (float)NTOK;
        a += ce * pi;
    }
    *p = a * 0.001f;
}

// ---------------- launch ----------------
extern "C" void kernel_launch(void* const* d_in, const int* in_sizes, int n_in,
                              void* d_out, int out_size) {
    (void)in_sizes; (void)n_in;
    const float* x   = (const float*)d_in[0];
    const float* gw  = (const float*)d_in[1];
    const float* wgt = (const float*)d_in[2];
    const float* wup = (const float*)d_in[3];
    const float* wdn = (const float*)d_in[4];
    const float* shg = (const float*)d_in[5];
    const float* shu = (const float*)d_in[6];
    const float* shd = (const float*)d_in[7];
    float* y = (float*)d_out;

    cudaFuncSetAttribute(gateup_mma, cudaFuncAttributeMaxDynamicSharedMemorySize, GU_SM);
    cudaFuncSetAttribute(down_mma,   cudaFuncAttributeMaxDynamicSharedMemorySize, DN_SM);

    // launch order keeps gateup_mma at index 3 (ncu capture slot)
    xconv_kernel<<<(NTOK * HDIM + 255) / 256, 256>>>(x);            // 0 (+ counter reset)
    const int NT4 = (NEXP + 1) * MDIM * HDIM / 4;
    wconv_all<<<dim3((NT4 + 255) / 256, 3), 256>>>(                 // 1
        (const float4*)wgt, (const float4*)wup, (const float4*)wdn,
        (const float4*)shg, (const float4*)shu, (const float4*)shd);
    gate_kernel<<<NTOK, 256>>>(x, gw);                              // 2
    gateup_mma<<<dim3(NTOK / 64, MDIM / 64, NEXP + 1), 128, GU_SM>>>();   // 3
    zeroy_kernel<<<(NTOK * HDIM + 255) / 256, 256>>>(y);            // 4
    down_mma<<<dim3(NTOK / 64, HDIM / 128, NEXP + 1), 128, DN_SM>>>(y);   // 5
    if (out_size > NTOK * HDIM)
        aux_kernel<<<1, 1>>>(y + NTOK * HDIM);                      // 6
}

// round 16
// speedup vs baseline: 1.0515x; 1.0515x over previous
#include <cuda_runtime.h>
#include <cuda_fp16.h>
#include <cstdint>

#define HDIM 2048
#define MDIM 1408
#define NEXP 8
#define NTOK 1024

// ---------------- device scratch ----------------
__device__ __half g_xh[NTOK * HDIM];                // x, single fp16 plane
__device__ __half g_act[(NEXP + 1) * NTOK * MDIM];  // activations, single fp16 plane
__device__ __half g_wgh[(NEXP + 1) * MDIM * HDIM];
__device__ __half g_wuh[(NEXP + 1) * MDIM * HDIM];
__device__ __half g_wdh[(NEXP + 1) * HDIM * MDIM];
__device__ int   g_tok[NEXP * NTOK];
__device__ float g_wt[NEXP * NTOK];
__device__ int   g_cnt[NEXP];
__device__ float g_pisum[NEXP];

// ---------------- helpers ----------------
__device__ __forceinline__ uint32_t smem_u32(const void* p) {
    uint32_t a;
    asm("{ .reg .u64 t; cvta.to.shared.u64 t, %1; cvt.u32.u64 %0, t; }" : "=r"(a) : "l"(p));
    return a;
}
__device__ __forceinline__ void cp16(uint32_t dst, const void* src) {
    asm volatile("cp.async.cg.shared.global [%0], [%1], 16;" :: "r"(dst), "l"(src));
}
#define CP_COMMIT() asm volatile("cp.async.commit_group;" ::: "memory")
#define CP_WAIT1()  asm volatile("cp.async.wait_group 1;" ::: "memory")
#define CP_WAIT2()  asm volatile("cp.async.wait_group 2;" ::: "memory")

#define LDSM4(r, addr)                                                                       \
    asm volatile("ldmatrix.sync.aligned.m8n8.x4.shared.b16 {%0,%1,%2,%3}, [%4];"             \
                 : "=r"((r)[0]), "=r"((r)[1]), "=r"((r)[2]), "=r"((r)[3]) : "r"(addr))
#define LDSM2(r, addr)                                                                       \
    asm volatile("ldmatrix.sync.aligned.m8n8.x2.shared.b16 {%0,%1}, [%2];"                   \
                 : "=r"((r)[0]), "=r"((r)[1]) : "r"(addr))
#define MMA(c, a, b)                                                                         \
    asm volatile("mma.sync.aligned.m16n8k16.row.col.f32.f16.f16.f32 "                        \
                 "{%0,%1,%2,%3},{%4,%5,%6,%7},{%8,%9},{%0,%1,%2,%3};"                        \
                 : "+f"((c)[0]), "+f"((c)[1]), "+f"((c)[2]), "+f"((c)[3])                    \
                 : "r"((a)[0]), "r"((a)[1]), "r"((a)[2]), "r"((a)[3]), "r"((b)[0]), "r"((b)[1]))

__device__ __forceinline__ uint32_t hpack2(float a, float b) {
    __half2 hp = __halves2half2(__float2half(a), __float2half(b));
    return *reinterpret_cast<uint32_t*>(&hp);
}

#define LDS_ROW 80   // 32 fp16 + 16B pad -> conflict-free ldmatrix

// ---------------- init / conversions ----------------
__global__ void zeroy_kernel(float* __restrict__ y) {
    int i = blockIdx.x * blockDim.x + threadIdx.x;
    if (i < NTOK * HDIM) y[i] = 0.f;
}

__global__ void xconv_kernel(const float* __restrict__ x) {
    int i = blockIdx.x * blockDim.x + threadIdx.x;
    if (i < NTOK * HDIM) g_xh[i] = __float2half(x[i]);
    if (i < NEXP) { g_cnt[i] = 0; g_pisum[i] = 0.f; }
}

__global__ __launch_bounds__(256)
void wconv_all(const float4* __restrict__ wg, const float4* __restrict__ wu,
               const float4* __restrict__ wd, const float4* __restrict__ sg,
               const float4* __restrict__ su, const float4* __restrict__ sd) {
    const int NE4 = NEXP * MDIM * HDIM / 4;
    const int NT4 = (NEXP + 1) * MDIM * HDIM / 4;
    int i = blockIdx.x * blockDim.x + threadIdx.x;
    if (i >= NT4) return;
    int which = blockIdx.y;
    __half* hb;
    const float4 *rsrc, *ssrc;
    if (which == 0)      { hb = g_wgh; rsrc = wg; ssrc = sg; }
    else if (which == 1) { hb = g_wuh; rsrc = wu; ssrc = su; }
    else                 { hb = g_wdh; rsrc = wd; ssrc = sd; }
    float4 v = (i < NE4) ? rsrc[i] : ssrc[i - NE4];
    uint2 h;
    h.x = hpack2(v.x, v.y);
    h.y = hpack2(v.z, v.w);
    ((uint2*)hb)[i] = h;
}

// ---------------- gate ----------------
__global__ __launch_bounds__(256)
void gate_kernel(const float* __restrict__ x, const float* __restrict__ gw) {
    const int t = blockIdx.x;
    const float* xr = x + (size_t)t * HDIM;
    float acc[NEXP];
#pragma unroll
    for (int e = 0; e < NEXP; e++) acc[e] = 0.f;
    for (int h = threadIdx.x; h < HDIM; h += 256) {
        float xv = xr[h];
#pragma unroll
        for (int e = 0; e < NEXP; e++) acc[e] = fmaf(xv, gw[e * HDIM + h], acc[e]);
    }
#pragma unroll
    for (int e = 0; e < NEXP; e++)
        for (int o = 16; o > 0; o >>= 1) acc[e] += __shfl_down_sync(0xffffffffu, acc[e], o);

    __shared__ float red[8][NEXP];
    int warp = threadIdx.x >> 5, lane = threadIdx.x & 31;
    if (lane == 0) {
#pragma unroll
        for (int e = 0; e < NEXP; e++) red[warp][e] = acc[e];
    }
    __syncthreads();
    if (threadIdx.x == 0) {
        float lg[NEXP];
#pragma unroll
        for (int e = 0; e < NEXP; e++) {
            float s = 0.f;
            for (int w = 0; w < 8; w++) s += red[w][e];
            lg[e] = s;
        }
        float mx = lg[0];
#pragma unroll
        for (int e = 1; e < NEXP; e++) mx = fmaxf(mx, lg[e]);
        float p[NEXP]; float den = 0.f;
#pragma unroll
        for (int e = 0; e < NEXP; e++) { p[e] = __expf(lg[e] - mx); den += p[e]; }
#pragma unroll
        for (int e = 0; e < NEXP; e++) p[e] /= den;
#pragma unroll
        for (int e = 0; e < NEXP; e++) atomicAdd(&g_pisum[e], p[e]);
        int i1 = 0;
#pragma unroll
        for (int e = 1; e < NEXP; e++) if (p[e] > p[i1]) i1 = e;
        int i2 = -1;
#pragma unroll
        for (int e = 0; e < NEXP; e++) {
            if (e == i1) continue;
            if (i2 < 0 || p[e] > p[i2]) i2 = e;
        }
        float w1 = p[i1], w2 = p[i2];
        float s2 = w1 + w2 + 1e-20f;
        w1 /= s2; w2 /= s2;
        int pos1 = atomicAdd(&g_cnt[i1], 1);
        g_tok[i1 * NTOK + pos1] = t; g_wt[i1 * NTOK + pos1] = w1;
        int pos2 = atomicAdd(&g_cnt[i2], 1);
        g_tok[i2 * NTOK + pos2] = t; g_wt[i2 * NTOK + pos2] = w2;
    }
}

// =======================================================================
// gateup: act = silu(X Wg^T) * (X Wu^T)
// tile 64x64, 128 thr, K chunk 32, 3-stage, 4 CTAs/SM   (R15 version)
// =======================================================================
#define GU_STAGE 15360
#define GU_A   0
#define GU_BG  5120
#define GU_BU  10240
#define GU_TOK (3 * GU_STAGE)
#define GU_SM  (GU_TOK + 256)

__global__ __launch_bounds__(128, 4)
void gateup_mma() {
    extern __shared__ __align__(128) char sm[];
    const int z = blockIdx.z;
    const bool SH = (z == NEXP);
    const int nrows = SH ? NTOK : g_cnt[z];
    const int row0 = blockIdx.x * 64;
    if (row0 >= nrows) return;
    const int n0 = blockIdx.y * 64;

    const int tid = threadIdx.x, wid = tid >> 5, lane = tid & 31;
    int* toks = (int*)(sm + GU_TOK);
    if (tid < 64) {
        int r = row0 + tid;
        toks[tid] = (r < nrows) ? (SH ? r : g_tok[z * NTOK + r]) : 0;
    }
    __syncthreads();

    const uint32_t sb = smem_u32(sm);

    // A cp: 2 thr/row, 2 cp16 each (64 rows x 64B)
    const int arow = tid >> 1, aseg = tid & 1;
    const __half* ap = g_xh + (size_t)toks[arow] * HDIM + aseg * 16;
    const uint32_t aD = sb + GU_A + arow * LDS_ROW + aseg * 32;

    // B cp: plane = tid>>6 (g,u), row = tid&63, 4 cp16 each
    const int bpl = tid >> 6, brow = tid & 63;
    const size_t bOff = ((size_t)z * MDIM + n0 + brow) * HDIM;
    const __half* pb = (bpl == 0 ? g_wgh : g_wuh) + bOff;
    const uint32_t bD = sb + (bpl == 0 ? GU_BG : GU_BU) + brow * LDS_ROW;

#define GU_CP(c) do { uint32_t o = ((c) % 3) * GU_STAGE; size_t ko = (size_t)(c) * 32; \
    cp16(aD + o,      ap + ko);      cp16(aD + o + 16, ap + ko + 8);                   \
    cp16(bD + o,      pb + ko);      cp16(bD + o + 16, pb + ko + 8);                   \
    cp16(bD + o + 32, pb + ko + 16); cp16(bD + o + 48, pb + ko + 24); } while (0)

    // fragments: warp grid 2m x 2n; warp tile 32x32 (dual g/u acc)
    const int wm = wid & 1, wn = wid >> 1;
    const uint32_t aOffL = (lane & 15) * LDS_ROW + (lane >> 4) * 16;
    const uint32_t bOffL = (lane & 7) * LDS_ROW + ((lane >> 3) & 1) * 16;
    const uint32_t aB = sb + GU_A + (wm * 32) * LDS_ROW + aOffL;
    const uint32_t bGB = sb + GU_BG + (wn * 32) * LDS_ROW + bOffL;
    const uint32_t bUB = sb + GU_BU + (wn * 32) * LDS_ROW + bOffL;

    float accg[2][4][4] = {}, accu[2][4][4] = {};

    const int NC = HDIM / 32;
    GU_CP(0); CP_COMMIT();
    GU_CP(1); CP_COMMIT();

    for (int c = 0; c < NC; c++) {
        const uint32_t so = (c % 3) * GU_STAGE;
        CP_WAIT1();
        __syncthreads();
        if (c + 2 < NC) GU_CP(c + 2);
        CP_COMMIT();   // one commit per iter (possibly empty) keeps wait_group invariant
#pragma unroll
        for (int ks = 0; ks < 2; ks++) {
            uint32_t ah[2][4];
#pragma unroll
            for (int i = 0; i < 2; i++)
                LDSM4(ah[i], aB + so + i * (16 * LDS_ROW) + ks * 32);
            uint32_t bgh[4][2], buh[4][2];
#pragma unroll
            for (int j = 0; j < 4; j++) {
                LDSM2(bgh[j], bGB + so + j * (8 * LDS_ROW) + ks * 32);
                LDSM2(buh[j], bUB + so + j * (8 * LDS_ROW) + ks * 32);
            }
#pragma unroll
            for (int i = 0; i < 2; i++)
#pragma unroll
                for (int j = 0; j < 4; j++) {
                    MMA(accg[i][j], ah[i], bgh[j]);
                    MMA(accu[i][j], ah[i], buh[j]);
                }
        }
    }

    // epilogue: silu(g)*u -> single fp16 plane
    const int mrow = wm * 32 + (lane >> 2);
    const int col0 = n0 + wn * 32 + (lane & 3) * 2;
#pragma unroll
    for (int i = 0; i < 2; i++)
#pragma unroll
        for (int j = 0; j < 4; j++) {
            int col = col0 + j * 8;
#pragma unroll
            for (int half = 0; half < 2; half++) {
                int r = row0 + mrow + i * 16 + half * 8;
                if (r < nrows) {
                    float gv0 = accg[i][j][half * 2],     uv0 = accu[i][j][half * 2];
                    float gv1 = accg[i][j][half * 2 + 1], uv1 = accu[i][j][half * 2 + 1];
                    float a0 = (gv0 / (1.f + __expf(-gv0))) * uv0;
                    float a1 = (gv1 / (1.f + __expf(-gv1))) * uv1;
                    size_t idx = ((size_t)z * NTOK + r) * MDIM + col;
                    *(uint32_t*)(g_act + idx) = hpack2(a0, a1);
                }
            }
        }
#undef GU_CP
}

// =======================================================================
// down: y[tok] += w * (act @ Wd^T)
// tile 128x128, 256 thr, K chunk 32, 4-stage, 2 CTAs/SM   (R14 version)
// =======================================================================
#define DN_STAGE 20480
#define DN_A   0
#define DN_B   10240
#define DN_TOK 81920
#define DN_WTS 82432
#define DN_SM  82944

__global__ __launch_bounds__(256, 2)
void down_mma(float* __restrict__ y) {
    extern __shared__ __align__(128) char sm[];
    const int z = blockIdx.z;
    const bool SH = (z == NEXP);
    const int nrows = SH ? NTOK : g_cnt[z];
    const int row0 = blockIdx.x * 128;
    if (row0 >= nrows) return;
    const int h0 = blockIdx.y * 128;

    const int tid = threadIdx.x, wid = tid >> 5, lane = tid & 31;
    int* toks = (int*)(sm + DN_TOK);
    float* wts = (float*)(sm + DN_WTS);
    if (tid < 128) {
        int r = row0 + tid;
        if (r < nrows) {
            toks[tid] = SH ? r : g_tok[z * NTOK + r];
            wts[tid]  = SH ? 1.f : g_wt[z * NTOK + r];
        } else { toks[tid] = 0; wts[tid] = 0.f; }
    }
    __syncthreads();

    const uint32_t sb = smem_u32(sm);

    const int arow = tid >> 1, aseg = tid & 1;
    const __half* ap = g_act + ((size_t)z * NTOK + row0 + arow) * MDIM + aseg * 16;
    const uint32_t aD = sb + DN_A + arow * LDS_ROW + aseg * 32;

    const size_t bOff = ((size_t)z * HDIM + h0 + arow) * MDIM + aseg * 16;
    const __half* pb = g_wdh + bOff;
    const uint32_t bD = sb + DN_B + arow * LDS_ROW + aseg * 32;

#define DN_CP(c) do { uint32_t o = ((c) & 3) * DN_STAGE; size_t ko = (size_t)(c) * 32; \
    cp16(aD + o,      ap + ko);      cp16(aD + o + 16, ap + ko + 8);                   \
    cp16(bD + o,      pb + ko);      cp16(bD + o + 16, pb + ko + 8); } while (0)

    const int wm = wid & 1, wn = wid >> 1;   // warp tile 64x32
    const uint32_t aOffL = (lane & 15) * LDS_ROW + (lane >> 4) * 16;
    const uint32_t bOffL = (lane & 7) * LDS_ROW + ((lane >> 3) & 1) * 16;
    const uint32_t aB = sb + DN_A + (wm * 64) * LDS_ROW + aOffL;
    const uint32_t bB = sb + DN_B + (wn * 32) * LDS_ROW + bOffL;

    float acc[4][4][4] = {};

    const int NC = MDIM / 32;
    DN_CP(0); CP_COMMIT();
    DN_CP(1); CP_COMMIT();
    DN_CP(2); CP_COMMIT();

    for (int c = 0; c < NC; c++) {
        const uint32_t so = (c & 3) * DN_STAGE;
        CP_WAIT2();
        __syncthreads();
        if (c + 3 < NC) DN_CP(c + 3);
        CP_COMMIT();
#pragma unroll
        for (int ks = 0; ks < 2; ks++) {
            uint32_t ah[4][4];
#pragma unroll
            for (int i = 0; i < 4; i++)
                LDSM4(ah[i], aB + so + i * (16 * LDS_ROW) + ks * 32);
            uint32_t bh[4][2];
#pragma unroll
            for (int j = 0; j < 4; j++)
                LDSM2(bh[j], bB + so + j * (8 * LDS_ROW) + ks * 32);
#pragma unroll
            for (int i = 0; i < 4; i++)
#pragma unroll
                for (int j = 0; j < 4; j++)
                    MMA(acc[i][j], ah[i], bh[j]);
        }
    }

    // epilogue: weighted atomic scatter
    const int mrow = wm * 64 + (lane >> 2);
    const int col0 = h0 + wn * 32 + (lane & 3) * 2;
#pragma unroll
    for (int i = 0; i < 4; i++)
#pragma unroll
        for (int half = 0; half < 2; half++) {
            int rl = mrow + i * 16 + half * 8;
            int r = row0 + rl;
            if (r < nrows) {
                float w = wts[rl];
                int tok = toks[rl];
                float* yp = y + (size_t)tok * HDIM;
#pragma unroll
                for (int j = 0; j < 4; j++) {
                    int col = col0 + j * 8;
                    atomicAdd(&yp[col],     acc[i][j][half * 2]     * w);
                    atomicAdd(&yp[col + 1], acc[i][j][half * 2 + 1] * w);
                }
            }
        }
#undef DN_CP
}

// ---------------- aux loss ----------------
__global__ void aux_kernel(float* __restrict__ p) {
    float a = 0.f;
#pragma unroll
    for (int e = 0; e < NEXP; e++) {
        float ce = (float)g_cnt[e] * ((float)NEXP / (float)(NTOK * 2));
        float pi = g_pisum[e] / (float)NTOK;
        a += ce * pi;
    }
    *p = a * 0.001f;
}

// ---------------- launch ----------------
extern "C" void kernel_launch(void* const* d_in, const int* in_sizes, int n_in,
                              void* d_out, int out_size) {
    (void)in_sizes; (void)n_in;
    const float* x   = (const float*)d_in[0];
    const float* gw  = (const float*)d_in[1];
    const float* wgt = (const float*)d_in[2];
    const float* wup = (const float*)d_in[3];
    const float* wdn = (const float*)d_in[4];
    const float* shg = (const float*)d_in[5];
    const float* shu = (const float*)d_in[6];
    const float* shd = (const float*)d_in[7];
    float* y = (float*)d_out;

    cudaFuncSetAttribute(gateup_mma, cudaFuncAttributeMaxDynamicSharedMemorySize, GU_SM);
    cudaFuncSetAttribute(down_mma,   cudaFuncAttributeMaxDynamicSharedMemorySize, DN_SM);

    // launch order keeps gateup_mma at index 3 (ncu capture slot)
    xconv_kernel<<<(NTOK * HDIM + 255) / 256, 256>>>(x);            // 0 (+ counter reset)
    const int NT4 = (NEXP + 1) * MDIM * HDIM / 4;
    wconv_all<<<dim3((NT4 + 255) / 256, 3), 256>>>(                 // 1
        (const float4*)wgt, (const float4*)wup, (const float4*)wdn,
        (const float4*)shg, (const float4*)shu, (const float4*)shd);
    gate_kernel<<<NTOK, 256>>>(x, gw);                              // 2
    gateup_mma<<<dim3(NTOK / 64, MDIM / 64, NEXP + 1), 128, GU_SM>>>();   // 3
    zeroy_kernel<<<(NTOK * HDIM + 255) / 256, 256>>>(y);            // 4
    down_mma<<<dim3(NTOK / 128, HDIM / 128, NEXP + 1), 256, DN_SM>>>(y);  // 5
    if (out_size > NTOK * HDIM)
        aux_kernel<<<1, 1>>>(y + NTOK * HDIM);                      // 6
}

// round 17
// speedup vs baseline: 1.0864x; 1.0332x over previous
#include <cuda_runtime.h>
#include <cuda_fp16.h>
#include <cstdint>

#define HDIM 2048
#define MDIM 1408
#define NEXP 8
#define NTOK 1024

// ---------------- device scratch ----------------
__device__ __half g_xh[NTOK * HDIM];                // x, single fp16 plane
__device__ __half g_act[(NEXP + 1) * NTOK * MDIM];  // activations, single fp16 plane
__device__ __half g_wgh[(NEXP + 1) * MDIM * HDIM];
__device__ __half g_wuh[(NEXP + 1) * MDIM * HDIM];
__device__ __half g_wdh[(NEXP + 1) * HDIM * MDIM];
__device__ int   g_tok[NEXP * NTOK];
__device__ float g_wt[NEXP * NTOK];
__device__ int   g_cnt[NEXP];
__device__ float g_pisum[NEXP];

// ---------------- helpers ----------------
__device__ __forceinline__ uint32_t smem_u32(const void* p) {
    uint32_t a;
    asm("{ .reg .u64 t; cvta.to.shared.u64 t, %1; cvt.u32.u64 %0, t; }" : "=r"(a) : "l"(p));
    return a;
}
__device__ __forceinline__ void cp16(uint32_t dst, const void* src) {
    asm volatile("cp.async.cg.shared.global [%0], [%1], 16;" :: "r"(dst), "l"(src));
}
#define CP_COMMIT() asm volatile("cp.async.commit_group;" ::: "memory")
#define CP_WAIT1()  asm volatile("cp.async.wait_group 1;" ::: "memory")
#define CP_WAIT2()  asm volatile("cp.async.wait_group 2;" ::: "memory")

#define LDSM4(r, addr)                                                                       \
    asm volatile("ldmatrix.sync.aligned.m8n8.x4.shared.b16 {%0,%1,%2,%3}, [%4];"             \
                 : "=r"((r)[0]), "=r"((r)[1]), "=r"((r)[2]), "=r"((r)[3]) : "r"(addr))
#define LDSM2(r, addr)                                                                       \
    asm volatile("ldmatrix.sync.aligned.m8n8.x2.shared.b16 {%0,%1}, [%2];"                   \
                 : "=r"((r)[0]), "=r"((r)[1]) : "r"(addr))
#define MMA(c, a, b)                                                                         \
    asm volatile("mma.sync.aligned.m16n8k16.row.col.f32.f16.f16.f32 "                        \
                 "{%0,%1,%2,%3},{%4,%5,%6,%7},{%8,%9},{%0,%1,%2,%3};"                        \
                 : "+f"((c)[0]), "+f"((c)[1]), "+f"((c)[2]), "+f"((c)[3])                    \
                 : "r"((a)[0]), "r"((a)[1]), "r"((a)[2]), "r"((a)[3]), "r"((b)[0]), "r"((b)[1]))

__device__ __forceinline__ uint32_t hpack2(float a, float b) {
    __half2 hp = __halves2half2(__float2half(a), __float2half(b));
    return *reinterpret_cast<uint32_t*>(&hp);
}

#define LDS_ROW 80   // 32 fp16 + 16B pad -> conflict-free ldmatrix

// ---------------- init / conversions ----------------
// x -> fp16, zero y, reset routing counters (runs BEFORE gate; y untouched until down)
__global__ void xconv_kernel(const float* __restrict__ x, float* __restrict__ y) {
    int i = blockIdx.x * blockDim.x + threadIdx.x;
    if (i < NTOK * HDIM) {
        g_xh[i] = __float2half(x[i]);
        y[i] = 0.f;
    }
    if (i < NEXP) { g_cnt[i] = 0; g_pisum[i] = 0.f; }
}

// all 6 weight tensors -> single fp16 plane each; 4 float4 per thread (MLP=4)
__global__ __launch_bounds__(256)
void wconv_all(const float4* __restrict__ wg, const float4* __restrict__ wu,
               const float4* __restrict__ wd, const float4* __restrict__ sg,
               const float4* __restrict__ su, const float4* __restrict__ sd) {
    const int NE4 = NEXP * MDIM * HDIM / 4;           // multiple of 4
    const int NT4 = (NEXP + 1) * MDIM * HDIM / 4;     // multiple of 4
    int base = (blockIdx.x * blockDim.x + threadIdx.x) * 4;
    if (base >= NT4) return;
    int which = blockIdx.y;
    __half* hb;
    const float4 *rsrc, *ssrc;
    if (which == 0)      { hb = g_wgh; rsrc = wg; ssrc = sg; }
    else if (which == 1) { hb = g_wuh; rsrc = wu; ssrc = su; }
    else                 { hb = g_wdh; rsrc = wd; ssrc = sd; }
    const bool routed = (base < NE4);   // group never straddles (NE4 % 4 == 0)
    const float4* src = routed ? (rsrc + base) : (ssrc + base - NE4);
    float4 v0 = src[0], v1 = src[1], v2 = src[2], v3 = src[3];
    uint4* hp = (uint4*)(hb + (size_t)base * 4);
    uint4 h0, h1;
    h0.x = hpack2(v0.x, v0.y); h0.y = hpack2(v0.z, v0.w);
    h0.z = hpack2(v1.x, v1.y); h0.w = hpack2(v1.z, v1.w);
    h1.x = hpack2(v2.x, v2.y); h1.y = hpack2(v2.z, v2.w);
    h1.z = hpack2(v3.x, v3.y); h1.w = hpack2(v3.z, v3.w);
    hp[0] = h0;
    hp[1] = h1;
}

// ---------------- gate ----------------
__global__ __launch_bounds__(256)
void gate_kernel(const float* __restrict__ x, const float* __restrict__ gw) {
    const int t = blockIdx.x;
    const float* xr = x + (size_t)t * HDIM;
    float acc[NEXP];
#pragma unroll
    for (int e = 0; e < NEXP; e++) acc[e] = 0.f;
    for (int h = threadIdx.x; h < HDIM; h += 256) {
        float xv = xr[h];
#pragma unroll
        for (int e = 0; e < NEXP; e++) acc[e] = fmaf(xv, gw[e * HDIM + h], acc[e]);
    }
#pragma unroll
    for (int e = 0; e < NEXP; e++)
        for (int o = 16; o > 0; o >>= 1) acc[e] += __shfl_down_sync(0xffffffffu, acc[e], o);

    __shared__ float red[8][NEXP];
    int warp = threadIdx.x >> 5, lane = threadIdx.x & 31;
    if (lane == 0) {
#pragma unroll
        for (int e = 0; e < NEXP; e++) red[warp][e] = acc[e];
    }
    __syncthreads();
    if (threadIdx.x == 0) {
        float lg[NEXP];
#pragma unroll
        for (int e = 0; e < NEXP; e++) {
            float s = 0.f;
            for (int w = 0; w < 8; w++) s += red[w][e];
            lg[e] = s;
        }
        float mx = lg[0];
#pragma unroll
        for (int e = 1; e < NEXP; e++) mx = fmaxf(mx, lg[e]);
        float p[NEXP]; float den = 0.f;
#pragma unroll
        for (int e = 0; e < NEXP; e++) { p[e] = __expf(lg[e] - mx); den += p[e]; }
#pragma unroll
        for (int e = 0; e < NEXP; e++) p[e] /= den;
#pragma unroll
        for (int e = 0; e < NEXP; e++) atomicAdd(&g_pisum[e], p[e]);
        int i1 = 0;
#pragma unroll
        for (int e = 1; e < NEXP; e++) if (p[e] > p[i1]) i1 = e;
        int i2 = -1;
#pragma unroll
        for (int e = 0; e < NEXP; e++) {
            if (e == i1) continue;
            if (i2 < 0 || p[e] > p[i2]) i2 = e;
        }
        float w1 = p[i1], w2 = p[i2];
        float s2 = w1 + w2 + 1e-20f;
        w1 /= s2; w2 /= s2;
        int pos1 = atomicAdd(&g_cnt[i1], 1);
        g_tok[i1 * NTOK + pos1] = t; g_wt[i1 * NTOK + pos1] = w1;
        int pos2 = atomicAdd(&g_cnt[i2], 1);
        g_tok[i2 * NTOK + pos2] = t; g_wt[i2 * NTOK + pos2] = w2;
    }
}

// =======================================================================
// gateup: act = silu(X Wg^T) * (X Wu^T)
// tile 64x64, 128 thr, K chunk 32, 3-stage, 4 CTAs/SM   (R15/R16 version)
// =======================================================================
#define GU_STAGE 15360
#define GU_A   0
#define GU_BG  5120
#define GU_BU  10240
#define GU_TOK (3 * GU_STAGE)
#define GU_SM  (GU_TOK + 256)

__global__ __launch_bounds__(128, 4)
void gateup_mma() {
    extern __shared__ __align__(128) char sm[];
    const int z = blockIdx.z;
    const bool SH = (z == NEXP);
    const int nrows = SH ? NTOK : g_cnt[z];
    const int row0 = blockIdx.x * 64;
    if (row0 >= nrows) return;
    const int n0 = blockIdx.y * 64;

    const int tid = threadIdx.x, wid = tid >> 5, lane = tid & 31;
    int* toks = (int*)(sm + GU_TOK);
    if (tid < 64) {
        int r = row0 + tid;
        toks[tid] = (r < nrows) ? (SH ? r : g_tok[z * NTOK + r]) : 0;
    }
    __syncthreads();

    const uint32_t sb = smem_u32(sm);

    // A cp: 2 thr/row, 2 cp16 each (64 rows x 64B)
    const int arow = tid >> 1, aseg = tid & 1;
    const __half* ap = g_xh + (size_t)toks[arow] * HDIM + aseg * 16;
    const uint32_t aD = sb + GU_A + arow * LDS_ROW + aseg * 32;

    // B cp: plane = tid>>6 (g,u), row = tid&63, 4 cp16 each
    const int bpl = tid >> 6, brow = tid & 63;
    const size_t bOff = ((size_t)z * MDIM + n0 + brow) * HDIM;
    const __half* pb = (bpl == 0 ? g_wgh : g_wuh) + bOff;
    const uint32_t bD = sb + (bpl == 0 ? GU_BG : GU_BU) + brow * LDS_ROW;

#define GU_CP(c) do { uint32_t o = ((c) % 3) * GU_STAGE; size_t ko = (size_t)(c) * 32; \
    cp16(aD + o,      ap + ko);      cp16(aD + o + 16, ap + ko + 8);                   \
    cp16(bD + o,      pb + ko);      cp16(bD + o + 16, pb + ko + 8);                   \
    cp16(bD + o + 32, pb + ko + 16); cp16(bD + o + 48, pb + ko + 24); } while (0)

    // fragments: warp grid 2m x 2n; warp tile 32x32 (dual g/u acc)
    const int wm = wid & 1, wn = wid >> 1;
    const uint32_t aOffL = (lane & 15) * LDS_ROW + (lane >> 4) * 16;
    const uint32_t bOffL = (lane & 7) * LDS_ROW + ((lane >> 3) & 1) * 16;
    const uint32_t aB = sb + GU_A + (wm * 32) * LDS_ROW + aOffL;
    const uint32_t bGB = sb + GU_BG + (wn * 32) * LDS_ROW + bOffL;
    const uint32_t bUB = sb + GU_BU + (wn * 32) * LDS_ROW + bOffL;

    float accg[2][4][4] = {}, accu[2][4][4] = {};

    const int NC = HDIM / 32;
    GU_CP(0); CP_COMMIT();
    GU_CP(1); CP_COMMIT();

    for (int c = 0; c < NC; c++) {
        const uint32_t so = (c % 3) * GU_STAGE;
        CP_WAIT1();
        __syncthreads();
        if (c + 2 < NC) GU_CP(c + 2);
        CP_COMMIT();   // one commit per iter (possibly empty) keeps wait_group invariant
#pragma unroll
        for (int ks = 0; ks < 2; ks++) {
            uint32_t ah[2][4];
#pragma unroll
            for (int i = 0; i < 2; i++)
                LDSM4(ah[i], aB + so + i * (16 * LDS_ROW) + ks * 32);
            uint32_t bgh[4][2], buh[4][2];
#pragma unroll
            for (int j = 0; j < 4; j++) {
                LDSM2(bgh[j], bGB + so + j * (8 * LDS_ROW) + ks * 32);
                LDSM2(buh[j], bUB + so + j * (8 * LDS_ROW) + ks * 32);
            }
#pragma unroll
            for (int i = 0; i < 2; i++)
#pragma unroll
                for (int j = 0; j < 4; j++) {
                    MMA(accg[i][j], ah[i], bgh[j]);
                    MMA(accu[i][j], ah[i], buh[j]);
                }
        }
    }

    // epilogue: silu(g)*u -> single fp16 plane
    const int mrow = wm * 32 + (lane >> 2);
    const int col0 = n0 + wn * 32 + (lane & 3) * 2;
#pragma unroll
    for (int i = 0; i < 2; i++)
#pragma unroll
        for (int j = 0; j < 4; j++) {
            int col = col0 + j * 8;
#pragma unroll
            for (int half = 0; half < 2; half++) {
                int r = row0 + mrow + i * 16 + half * 8;
                if (r < nrows) {
                    float gv0 = accg[i][j][half * 2],     uv0 = accu[i][j][half * 2];
                    float gv1 = accg[i][j][half * 2 + 1], uv1 = accu[i][j][half * 2 + 1];
                    float a0 = (gv0 / (1.f + __expf(-gv0))) * uv0;
                    float a1 = (gv1 / (1.f + __expf(-gv1))) * uv1;
                    size_t idx = ((size_t)z * NTOK + r) * MDIM + col;
                    *(uint32_t*)(g_act + idx) = hpack2(a0, a1);
                }
            }
        }
#undef GU_CP
}

// =======================================================================
// down: y[tok] += w * (act @ Wd^T)
// tile 128x128, 256 thr, K chunk 32, 4-stage, 2 CTAs/SM   (R14/R16 version)
// =======================================================================
#define DN_STAGE 20480
#define DN_A   0
#define DN_B   10240
#define DN_TOK 81920
#define DN_WTS 82432
#define DN_SM  82944

__global__ __launch_bounds__(256, 2)
void down_mma(float* __restrict__ y) {
    extern __shared__ __align__(128) char sm[];
    const int z = blockIdx.z;
    const bool SH = (z == NEXP);
    const int nrows = SH ? NTOK : g_cnt[z];
    const int row0 = blockIdx.x * 128;
    if (row0 >= nrows) return;
    const int h0 = blockIdx.y * 128;

    const int tid = threadIdx.x, wid = tid >> 5, lane = tid & 31;
    int* toks = (int*)(sm + DN_TOK);
    float* wts = (float*)(sm + DN_WTS);
    if (tid < 128) {
        int r = row0 + tid;
        if (r < nrows) {
            toks[tid] = SH ? r : g_tok[z * NTOK + r];
            wts[tid]  = SH ? 1.f : g_wt[z * NTOK + r];
        } else { toks[tid] = 0; wts[tid] = 0.f; }
    }
    __syncthreads();

    const uint32_t sb = smem_u32(sm);

    const int arow = tid >> 1, aseg = tid & 1;
    const __half* ap = g_act + ((size_t)z * NTOK + row0 + arow) * MDIM + aseg * 16;
    const uint32_t aD = sb + DN_A + arow * LDS_ROW + aseg * 32;

    const size_t bOff = ((size_t)z * HDIM + h0 + arow) * MDIM + aseg * 16;
    const __half* pb = g_wdh + bOff;
    const uint32_t bD = sb + DN_B + arow * LDS_ROW + aseg * 32;

#define DN_CP(c) do { uint32_t o = ((c) & 3) * DN_STAGE; size_t ko = (size_t)(c) * 32; \
    cp16(aD + o,      ap + ko);      cp16(aD + o + 16, ap + ko + 8);                   \
    cp16(bD + o,      pb + ko);      cp16(bD + o + 16, pb + ko + 8); } while (0)

    const int wm = wid & 1, wn = wid >> 1;   // warp tile 64x32
    const uint32_t aOffL = (lane & 15) * LDS_ROW + (lane >> 4) * 16;
    const uint32_t bOffL = (lane & 7) * LDS_ROW + ((lane >> 3) & 1) * 16;
    const uint32_t aB = sb + DN_A + (wm * 64) * LDS_ROW + aOffL;
    const uint32_t bB = sb + DN_B + (wn * 32) * LDS_ROW + bOffL;

    float acc[4][4][4] = {};

    const int NC = MDIM / 32;
    DN_CP(0); CP_COMMIT();
    DN_CP(1); CP_COMMIT();
    DN_CP(2); CP_COMMIT();

    for (int c = 0; c < NC; c++) {
        const uint32_t so = (c & 3) * DN_STAGE;
        CP_WAIT2();
        __syncthreads();
        if (c + 3 < NC) DN_CP(c + 3);
        CP_COMMIT();
#pragma unroll
        for (int ks = 0; ks < 2; ks++) {
            uint32_t ah[4][4];
#pragma unroll
            for (int i = 0; i < 4; i++)
                LDSM4(ah[i], aB + so + i * (16 * LDS_ROW) + ks * 32);
            uint32_t bh[4][2];
#pragma unroll
            for (int j = 0; j < 4; j++)
                LDSM2(bh[j], bB + so + j * (8 * LDS_ROW) + ks * 32);
#pragma unroll
            for (int i = 0; i < 4; i++)
#pragma unroll
                for (int j = 0; j < 4; j++)
                    MMA(acc[i][j], ah[i], bh[j]);
        }
    }

    // epilogue: weighted atomic scatter
    const int mrow = wm * 64 + (lane >> 2);
    const int col0 = h0 + wn * 32 + (lane & 3) * 2;
#pragma unroll
    for (int i = 0; i < 4; i++)
#pragma unroll
        for (int half = 0; half < 2; half++) {
            int rl = mrow + i * 16 + half * 8;
            int r = row0 + rl;
            if (r < nrows) {
                float w = wts[rl];
                int tok = toks[rl];
                float* yp = y + (size_t)tok * HDIM;
#pragma unroll
                for (int j = 0; j < 4; j++) {
                    int col = col0 + j * 8;
                    atomicAdd(&yp[col],     acc[i][j][half * 2]     * w);
                    atomicAdd(&yp[col + 1], acc[i][j][half * 2 + 1] * w);
                }
            }
        }
#undef DN_CP
}

// ---------------- aux loss ----------------
__global__ void aux_kernel(float* __restrict__ p) {
    float a = 0.f;
#pragma unroll
    for (int e = 0; e < NEXP; e++) {
        float ce = (float)g_cnt[e] * ((float)NEXP / (float)(NTOK * 2));
        float pi = g_pisum[e] / (float)NTOK;
        a += ce * pi;
    }
    *p = a * 0.001f;
}

// ---------------- launch ----------------
extern "C" void kernel_launch(void* const* d_in, const int* in_sizes, int n_in,
                              void* d_out, int out_size) {
    (void)in_sizes; (void)n_in;
    const float* x   = (const float*)d_in[0];
    const float* gw  = (const float*)d_in[1];
    const float* wgt = (const float*)d_in[2];
    const float* wup = (const float*)d_in[3];
    const float* wdn = (const float*)d_in[4];
    const float* shg = (const float*)d_in[5];
    const float* shu = (const float*)d_in[6];
    const float* shd = (const float*)d_in[7];
    float* y = (float*)d_out;

    cudaFuncSetAttribute(gateup_mma, cudaFuncAttributeMaxDynamicSharedMemorySize, GU_SM);
    cudaFuncSetAttribute(down_mma,   cudaFuncAttributeMaxDynamicSharedMemorySize, DN_SM);

    // launch order keeps gateup_mma at index 3 (ncu capture slot)
    xconv_kernel<<<(NTOK * HDIM + 255) / 256, 256>>>(x, y);         // 0 (x->fp16, zero y, reset counters)
    const int NT4 = (NEXP + 1) * MDIM * HDIM / 4;
    wconv_all<<<dim3((NT4 / 4 + 255) / 256, 3), 256>>>(             // 1 (4x float4 per thread)
        (const float4*)wgt, (const float4*)wup, (const float4*)wdn,
        (const float4*)shg, (const float4*)shu, (const float4*)shd);
    gate_kernel<<<NTOK, 256>>>(x, gw);                              // 2
    gateup_mma<<<dim3(NTOK / 64, MDIM / 64, NEXP + 1), 128, GU_SM>>>();   // 3
    down_mma<<<dim3(NTOK / 128, HDIM / 128, NEXP + 1), 256, DN_SM>>>(y);  // 4
    if (out_size > NTOK * HDIM)
        aux_kernel<<<1, 1>>>(y + NTOK * HDIM);                      // 5
}